// round 10
// baseline (speedup 1.0000x reference)
#include <cuda_runtime.h>

// dis_loss: mean over (B*21) per-joint Euclidean distances of [B,21,3] fp32.
// 132 MB read, 4 B write. Key change vs R6: fully COALESCED LDG.128
// (warp-tiled, lane-contiguous) instead of thread-contiguous 48B-stride loads
// that caused 12 L1tex wavefronts + replays per load. Joint regrouping done
// with 6 shuffles/thread/tile on register-resident squared diffs.

#define B_ROWS      262144
#define N_JOINTS    21
#define TOTAL_F     (B_ROWS * N_JOINTS * 3)     // 16,515,072 floats per tensor
#define TILE_FLOATS 384                          // per warp: 96 float4 = 128 joints
#define N_TILES     (TOTAL_F / TILE_FLOATS)      // 43,008 exact
#define THREADS     256
#define WARPS_PB    (THREADS / 32)
#define GRID        1184

__device__ float    g_acc;
__device__ unsigned g_count;

__device__ __forceinline__ float sqd(float a, float b) {
    float d = a - b;
    return d * d;
}

__global__ void __launch_bounds__(THREADS)
dis_loss_kernel(const float4* __restrict__ pred,
                const float4* __restrict__ tgt,
                float* __restrict__ out) {
    const unsigned FULL = 0xFFFFFFFFu;
    const int lane  = threadIdx.x & 31;
    const int wid   = (blockIdx.x * WARPS_PB) + (threadIdx.x >> 5);
    const int nwarp = GRID * WARPS_PB;
    const int nl    = (lane + 1) & 31;
    const int lm3   = lane % 3;
    // joint-start mode per segment: m = (2*seg + lane) % 3
    const int m0 = lm3;
    const int m1 = (lm3 + 2 >= 3) ? lm3 - 1 : lm3 + 2;
    const int m2 = (lm3 + 1 >= 3) ? lm3 - 2 : lm3 + 1;

    float acc = 0.0f;

    for (int tile = wid; tile < N_TILES; tile += nwarp) {
        const float4* pb = pred + tile * 96;
        const float4* tb = tgt  + tile * 96;
        // 6 fully coalesced LDG.128 (lane-contiguous within each segment)
        float4 p0 = pb[lane];       float4 p1 = pb[32 + lane];  float4 p2 = pb[64 + lane];
        float4 t0 = tb[lane];       float4 t1 = tb[32 + lane];  float4 t2 = tb[64 + lane];

        // squared diffs per segment: lane l holds elements 128*seg + 4l .. +3
        float4 q0, q1, q2;
        q0.x = sqd(p0.x, t0.x); q0.y = sqd(p0.y, t0.y); q0.z = sqd(p0.z, t0.z); q0.w = sqd(p0.w, t0.w);
        q1.x = sqd(p1.x, t1.x); q1.y = sqd(p1.y, t1.y); q1.z = sqd(p1.z, t1.z); q1.w = sqd(p1.w, t1.w);
        q2.x = sqd(p2.x, t2.x); q2.y = sqd(p2.y, t2.y); q2.z = sqd(p2.z, t2.z); q2.w = sqd(p2.w, t2.w);

        // neighbor elements: lane l's s4,s5 = lane l+1's s0,s1 (same segment),
        // except lane 31 which takes next segment's lane 0.
        float sh0a = __shfl_sync(FULL, q0.x, nl);
        float sh0b = __shfl_sync(FULL, q0.y, nl);
        float sh1a = __shfl_sync(FULL, q1.x, nl);
        float sh1b = __shfl_sync(FULL, q1.y, nl);
        float sh2a = __shfl_sync(FULL, q2.x, nl);
        float sh2b = __shfl_sync(FULL, q2.y, nl);

        const bool last = (lane == 31);

        // ---- segment 0 ----
        {
            float s4 = last ? sh1a : sh0a;
            float s5 = last ? sh1b : sh0b;
            float jm = (m0 == 0) ? (q0.x + q0.y + q0.z)
                     : (m0 == 1) ? (q0.z + q0.w + s4)
                                 : (q0.y + q0.z + q0.w);
            acc += sqrtf(jm);
            if (m0 == 0) acc += sqrtf(q0.w + s4 + s5);
        }
        // ---- segment 1 ----
        {
            float s4 = last ? sh2a : sh1a;
            float s5 = last ? sh2b : sh1b;
            float jm = (m1 == 0) ? (q1.x + q1.y + q1.z)
                     : (m1 == 1) ? (q1.z + q1.w + s4)
                                 : (q1.y + q1.z + q1.w);
            acc += sqrtf(jm);
            if (m1 == 0) acc += sqrtf(q1.w + s4 + s5);
        }
        // ---- segment 2 ---- (lane 31 has m2==2: never touches s4/s5; tile is
        // joint-aligned so nothing crosses the tile boundary)
        {
            float s4 = sh2a;
            float s5 = sh2b;
            float jm = (m2 == 0) ? (q2.x + q2.y + q2.z)
                     : (m2 == 1) ? (q2.z + q2.w + s4)
                                 : (q2.y + q2.z + q2.w);
            acc += sqrtf(jm);
            if (m2 == 0) acc += sqrtf(q2.w + s4 + s5);
        }
    }

    // Warp reduction
    #pragma unroll
    for (int off = 16; off > 0; off >>= 1)
        acc += __shfl_xor_sync(FULL, acc, off);

    // Block reduction
    __shared__ float warp_sums[WARPS_PB];
    const int warp = threadIdx.x >> 5;
    if (lane == 0) warp_sums[warp] = acc;
    __syncthreads();

    __shared__ bool is_last;
    if (threadIdx.x == 0) {
        float bsum = 0.0f;
        #pragma unroll
        for (int w = 0; w < WARPS_PB; w++) bsum += warp_sums[w];
        atomicAdd(&g_acc, bsum);
        __threadfence();
        unsigned prev = atomicAdd(&g_count, 1u);
        is_last = (prev == (unsigned)(GRID - 1));
    }
    __syncthreads();

    if (is_last && threadIdx.x == 0) {
        float total = atomicAdd(&g_acc, 0.0f);
        out[0] = total * (1.0f / (float)((long long)B_ROWS * N_JOINTS));
        g_acc   = 0.0f;
        g_count = 0u;
    }
}

extern "C" void kernel_launch(void* const* d_in, const int* in_sizes, int n_in,
                              void* d_out, int out_size) {
    const float4* pred = (const float4*)d_in[0];
    const float4* tgt  = (const float4*)d_in[1];
    float* out = (float*)d_out;
    dis_loss_kernel<<<GRID, THREADS>>>(pred, tgt, out);
}

// round 11
// speedup vs baseline: 1.0094x; 1.0094x over previous
#include <cuda_runtime.h>

// dis_loss: mean over (B*21) per-joint Euclidean distances of [B,21,3] fp32.
// 132 MB read, 4 B write. Key change vs R6: fully COALESCED LDG.128
// (warp-tiled, lane-contiguous) instead of thread-contiguous 48B-stride loads
// that caused 12 L1tex wavefronts + replays per load. Joint regrouping done
// with 6 shuffles/thread/tile on register-resident squared diffs.

#define B_ROWS      262144
#define N_JOINTS    21
#define TOTAL_F     (B_ROWS * N_JOINTS * 3)     // 16,515,072 floats per tensor
#define TILE_FLOATS 384                          // per warp: 96 float4 = 128 joints
#define N_TILES     (TOTAL_F / TILE_FLOATS)      // 43,008 exact
#define THREADS     256
#define WARPS_PB    (THREADS / 32)
#define GRID        1184

__device__ float    g_acc;
__device__ unsigned g_count;

__device__ __forceinline__ float sqd(float a, float b) {
    float d = a - b;
    return d * d;
}

__global__ void __launch_bounds__(THREADS)
dis_loss_kernel(const float4* __restrict__ pred,
                const float4* __restrict__ tgt,
                float* __restrict__ out) {
    const unsigned FULL = 0xFFFFFFFFu;
    const int lane  = threadIdx.x & 31;
    const int wid   = (blockIdx.x * WARPS_PB) + (threadIdx.x >> 5);
    const int nwarp = GRID * WARPS_PB;
    const int nl    = (lane + 1) & 31;
    const int lm3   = lane % 3;
    // joint-start mode per segment: m = (2*seg + lane) % 3
    const int m0 = lm3;
    const int m1 = (lm3 + 2 >= 3) ? lm3 - 1 : lm3 + 2;
    const int m2 = (lm3 + 1 >= 3) ? lm3 - 2 : lm3 + 1;

    float acc = 0.0f;

    for (int tile = wid; tile < N_TILES; tile += nwarp) {
        const float4* pb = pred + tile * 96;
        const float4* tb = tgt  + tile * 96;
        // 6 fully coalesced LDG.128 (lane-contiguous within each segment)
        float4 p0 = pb[lane];       float4 p1 = pb[32 + lane];  float4 p2 = pb[64 + lane];
        float4 t0 = tb[lane];       float4 t1 = tb[32 + lane];  float4 t2 = tb[64 + lane];

        // squared diffs per segment: lane l holds elements 128*seg + 4l .. +3
        float4 q0, q1, q2;
        q0.x = sqd(p0.x, t0.x); q0.y = sqd(p0.y, t0.y); q0.z = sqd(p0.z, t0.z); q0.w = sqd(p0.w, t0.w);
        q1.x = sqd(p1.x, t1.x); q1.y = sqd(p1.y, t1.y); q1.z = sqd(p1.z, t1.z); q1.w = sqd(p1.w, t1.w);
        q2.x = sqd(p2.x, t2.x); q2.y = sqd(p2.y, t2.y); q2.z = sqd(p2.z, t2.z); q2.w = sqd(p2.w, t2.w);

        // neighbor elements: lane l's s4,s5 = lane l+1's s0,s1 (same segment),
        // except lane 31 which takes next segment's lane 0.
        float sh0a = __shfl_sync(FULL, q0.x, nl);
        float sh0b = __shfl_sync(FULL, q0.y, nl);
        float sh1a = __shfl_sync(FULL, q1.x, nl);
        float sh1b = __shfl_sync(FULL, q1.y, nl);
        float sh2a = __shfl_sync(FULL, q2.x, nl);
        float sh2b = __shfl_sync(FULL, q2.y, nl);

        const bool last = (lane == 31);

        // ---- segment 0 ----
        {
            float s4 = last ? sh1a : sh0a;
            float s5 = last ? sh1b : sh0b;
            float jm = (m0 == 0) ? (q0.x + q0.y + q0.z)
                     : (m0 == 1) ? (q0.z + q0.w + s4)
                                 : (q0.y + q0.z + q0.w);
            acc += sqrtf(jm);
            if (m0 == 0) acc += sqrtf(q0.w + s4 + s5);
        }
        // ---- segment 1 ----
        {
            float s4 = last ? sh2a : sh1a;
            float s5 = last ? sh2b : sh1b;
            float jm = (m1 == 0) ? (q1.x + q1.y + q1.z)
                     : (m1 == 1) ? (q1.z + q1.w + s4)
                                 : (q1.y + q1.z + q1.w);
            acc += sqrtf(jm);
            if (m1 == 0) acc += sqrtf(q1.w + s4 + s5);
        }
        // ---- segment 2 ---- (lane 31 has m2==2: never touches s4/s5; tile is
        // joint-aligned so nothing crosses the tile boundary)
        {
            float s4 = sh2a;
            float s5 = sh2b;
            float jm = (m2 == 0) ? (q2.x + q2.y + q2.z)
                     : (m2 == 1) ? (q2.z + q2.w + s4)
                                 : (q2.y + q2.z + q2.w);
            acc += sqrtf(jm);
            if (m2 == 0) acc += sqrtf(q2.w + s4 + s5);
        }
    }

    // Warp reduction
    #pragma unroll
    for (int off = 16; off > 0; off >>= 1)
        acc += __shfl_xor_sync(FULL, acc, off);

    // Block reduction
    __shared__ float warp_sums[WARPS_PB];
    const int warp = threadIdx.x >> 5;
    if (lane == 0) warp_sums[warp] = acc;
    __syncthreads();

    __shared__ bool is_last;
    if (threadIdx.x == 0) {
        float bsum = 0.0f;
        #pragma unroll
        for (int w = 0; w < WARPS_PB; w++) bsum += warp_sums[w];
        atomicAdd(&g_acc, bsum);
        __threadfence();
        unsigned prev = atomicAdd(&g_count, 1u);
        is_last = (prev == (unsigned)(GRID - 1));
    }
    __syncthreads();

    if (is_last && threadIdx.x == 0) {
        float total = atomicAdd(&g_acc, 0.0f);
        out[0] = total * (1.0f / (float)((long long)B_ROWS * N_JOINTS));
        g_acc   = 0.0f;
        g_count = 0u;
    }
}

extern "C" void kernel_launch(void* const* d_in, const int* in_sizes, int n_in,
                              void* d_out, int out_size) {
    const float4* pred = (const float4*)d_in[0];
    const float4* tgt  = (const float4*)d_in[1];
    float* out = (float*)d_out;
    dis_loss_kernel<<<GRID, THREADS>>>(pred, tgt, out);
}